// round 6
// baseline (speedup 1.0000x reference)
#include <cuda_runtime.h>
#include <math.h>

#define T_TOK 4096
#define NH 1024          // hidden
#define NI 512           // intermediate
#define NE 16            // real experts
#define NSLOT 32         // real + zero slots
#define TOPK 4
#define MAXP 4096        // max pairs per expert (<= T)

#define BK 16

// ---- static device scratch (no runtime allocation allowed) ----
__device__ int   g_cnt[NE];                       // pairs per expert
__device__ int   g_tok[NE * MAXP];                // token index per pair slot
__device__ float g_wt [NE * MAXP];                // routing weight per pair slot
__device__ int   g_tk_n[T_TOK];                   // real experts chosen per token
__device__ int   g_tk_pair[T_TOK * TOPK];         // pair indices per token (topk order)
__device__ float g_act [(size_t)NE * MAXP * NI];  // SwiGLU activations
__device__ float g_pout[(size_t)NE * MAXP * NH];  // per-pair down output

// ---------------------------------------------------------------------------
__device__ __forceinline__ unsigned f2tf(float f) {
    unsigned r;
    asm("cvt.rna.tf32.f32 %0, %1;" : "=r"(r) : "f"(f));
    return r;
}

__device__ __forceinline__ void mma_tf32(float* d, const uint4& a, const uint2& b) {
    asm volatile(
        "mma.sync.aligned.m16n8k8.row.col.f32.tf32.tf32.f32 "
        "{%0,%1,%2,%3}, {%4,%5,%6,%7}, {%8,%9}, {%0,%1,%2,%3};"
        : "+f"(d[0]), "+f"(d[1]), "+f"(d[2]), "+f"(d[3])
        : "r"(a.x), "r"(a.y), "r"(a.z), "r"(a.w), "r"(b.x), "r"(b.y));
}

// ---------------------------------------------------------------------------
__global__ void reset_kernel() {
    int i = threadIdx.x;
    if (i < NE) g_cnt[i] = 0;
}

// ---------------------------------------------------------------------------
// Router: one block (256 threads) per token.
__global__ void router_kernel(const float* __restrict__ x,
                              const float* __restrict__ rw,
                              const float* __restrict__ bias,
                              float* __restrict__ out) {
    int t = blockIdx.x;
    __shared__ float sc[NSLOT];
    __shared__ float s_zero;
    int tid  = threadIdx.x;           // 256
    int slot = tid >> 3;              // 32 slots, 8 threads each
    int sub  = tid & 7;
    const float* xr = x  + (size_t)t * NH;
    const float* wr = rw + (size_t)slot * NH;

    float acc = 0.f;
    for (int h = sub * 4; h < NH; h += 32) {
        float4 xv = *reinterpret_cast<const float4*>(xr + h);
        float4 wv = *reinterpret_cast<const float4*>(wr + h);
        acc += xv.x * wv.x + xv.y * wv.y + xv.z * wv.z + xv.w * wv.w;
    }
    acc += __shfl_down_sync(0xffffffffu, acc, 4, 8);
    acc += __shfl_down_sync(0xffffffffu, acc, 2, 8);
    acc += __shfl_down_sync(0xffffffffu, acc, 1, 8);
    if (sub == 0) sc[slot] = acc;
    __syncthreads();

    if (tid == 0) {
        float mx = -1e30f;
        for (int i = 0; i < NSLOT; i++) mx = fmaxf(mx, sc[i]);
        float e[NSLOT], sum = 0.f;
        for (int i = 0; i < NSLOT; i++) { e[i] = expf(sc[i] - mx); sum += e[i]; }
        float inv = 1.f / sum;
        float sb[NSLOT];
        for (int i = 0; i < NSLOT; i++) {
            sc[i] = e[i] * inv;            // raw score (weight source)
            sb[i] = sc[i] + bias[i];       // selection score
        }
        float zero_w = 0.f;
        int tkn = 0;
        for (int kk = 0; kk < TOPK; kk++) {
            int bi = 0; float bv = -1e30f;
            for (int i = 0; i < NSLOT; i++)
                if (sb[i] > bv) { bv = sb[i]; bi = i; }
            sb[bi] = -1e30f;
            float w = sc[bi];
            if (bi < NE) {
                int s2 = atomicAdd(&g_cnt[bi], 1);
                g_tok[bi * MAXP + s2] = t;
                g_wt [bi * MAXP + s2] = w;
                g_tk_pair[t * TOPK + tkn] = bi * MAXP + s2;
                tkn++;
            } else {
                zero_w += w;
            }
        }
        g_tk_n[t] = tkn;
        s_zero = zero_w;
    }
    __syncthreads();

    float zw = s_zero;
    for (int h = tid; h < NH; h += 256)
        out[(size_t)t * NH + h] = zw * xr[h];
}

// ---------------------------------------------------------------------------
// GEMM1 (tf32 TC): act = silu(X.Wg)*(X.Wu).  Block 128x128, BK=16.
// 8 warps as 2(m) x 4(n); warp tile 64x32 per matrix (A fragments shared).
// Fragment-permuted smem; double-buffered; register prefetch.
#define G1_SA (2 * 8 * 32 * 4)     // 2048 unsigned per buffer (128x16)
#define G1_SB (2 * 16 * 32 * 2)    // 2048 unsigned per buffer (16x128)

__global__ __launch_bounds__(256) void gemm1_tc(const float* __restrict__ x,
                                                const float* __restrict__ wg,
                                                const float* __restrict__ wu) {
    int e    = blockIdx.z;
    int cnt  = g_cnt[e];
    int row0 = blockIdx.y * 128;
    if (row0 >= cnt) return;
    int col0 = blockIdx.x * 128;

    __shared__ unsigned sA [2 * G1_SA];   // 16KB
    __shared__ unsigned sBg[2 * G1_SB];   // 16KB
    __shared__ unsigned sBu[2 * G1_SB];   // 16KB

    int tid  = threadIdx.x;
    int lane = tid & 31;
    int wid  = tid >> 5;
    int wm   = wid >> 2;      // 0..1 -> rows wm*64
    int wn   = wid & 3;       // 0..3 -> cols wn*32

    // --- A loader: 2 float4/thread ---
    int tok[2];
    unsigned abase[2];
    int ac[2];
#pragma unroll
    for (int it = 0; it < 2; it++) {
        int f = tid + 256 * it;
        int r = f >> 2;
        int c = (f & 3) * 4;
        ac[it] = c;
        int rr = row0 + r;
        tok[it] = (rr < cnt) ? g_tok[e * MAXP + rr] : -1;
        int k8  = c >> 3;
        int reg = ((r >> 3) & 1) + 2 * ((c >> 2) & 1);
        abase[it] = (((unsigned)k8 * 8 + (r >> 4)) * 32 + (r & 7) * 4) * 4 + reg;
    }
    // --- B loader: 2 float4/thread per matrix; krow = f>>5, ncol = (f&31)*4 ---
    const float* wgP[2];
    const float* wuP[2];
    unsigned bbase[2];
#pragma unroll
    for (int it = 0; it < 2; it++) {
        int f    = tid + 256 * it;
        int krow = f >> 5;            // 0..15
        int ncol = (f & 31) * 4;      // 0..124
        wgP[it] = wg + (size_t)e * NH * NI + (size_t)krow * NI + col0 + ncol;
        wuP[it] = wu + (size_t)e * NH * NI + (size_t)krow * NI + col0 + ncol;
        int k8  = krow >> 3;
        int kk  = krow & 7;
        bbase[it] = (((unsigned)k8 * 16 + (ncol >> 3)) * 32 + (ncol & 7) * 4 + (kk & 3)) * 2
                    + (kk >> 2);
    }

    float dg[4][4][4] = {};
    float du[4][4][4] = {};

    float4 pA[2], pG[2], pU[2];
#pragma unroll
    for (int it = 0; it < 2; it++) {
        pA[it] = make_float4(0.f, 0.f, 0.f, 0.f);
        if (tok[it] >= 0)
            pA[it] = *reinterpret_cast<const float4*>(x + (size_t)tok[it] * NH + ac[it]);
        pG[it] = *reinterpret_cast<const float4*>(wgP[it]);
        pU[it] = *reinterpret_cast<const float4*>(wuP[it]);
    }
#pragma unroll
    for (int it = 0; it < 2; it++) {
        sA[abase[it] + 0]  = f2tf(pA[it].x);
        sA[abase[it] + 4]  = f2tf(pA[it].y);
        sA[abase[it] + 8]  = f2tf(pA[it].z);
        sA[abase[it] + 12] = f2tf(pA[it].w);
        sBg[bbase[it] + 0]  = f2tf(pG[it].x);  sBg[bbase[it] + 8]  = f2tf(pG[it].y);
        sBg[bbase[it] + 16] = f2tf(pG[it].z);  sBg[bbase[it] + 24] = f2tf(pG[it].w);
        sBu[bbase[it] + 0]  = f2tf(pU[it].x);  sBu[bbase[it] + 8]  = f2tf(pU[it].y);
        sBu[bbase[it] + 16] = f2tf(pU[it].z);  sBu[bbase[it] + 24] = f2tf(pU[it].w);
    }
    __syncthreads();

    const int NIT = NH / BK;  // 64
    for (int iter = 0; iter < NIT; iter++) {
        int buf = iter & 1;
        if (iter + 1 < NIT) {
            int k0 = (iter + 1) * BK;
#pragma unroll
            for (int it = 0; it < 2; it++) {
                pA[it] = make_float4(0.f, 0.f, 0.f, 0.f);
                if (tok[it] >= 0)
                    pA[it] = *reinterpret_cast<const float4*>(
                                 x + (size_t)tok[it] * NH + k0 + ac[it]);
                pG[it] = *reinterpret_cast<const float4*>(wgP[it] + (size_t)k0 * NI);
                pU[it] = *reinterpret_cast<const float4*>(wuP[it] + (size_t)k0 * NI);
            }
        }

        unsigned aoff = (unsigned)buf * G1_SA;
        unsigned boff = (unsigned)buf * G1_SB;
#pragma unroll
        for (int k8 = 0; k8 < 2; k8++) {
            uint4 a[4];
#pragma unroll
            for (int m = 0; m < 4; m++)
                a[m] = *reinterpret_cast<uint4*>(
                    &sA[aoff + (((unsigned)k8 * 8 + (wm * 4 + m)) * 32 + lane) * 4]);
            uint2 bg[4], bu[4];
#pragma unroll
            for (int n = 0; n < 4; n++) {
                bg[n] = *reinterpret_cast<uint2*>(
                    &sBg[boff + (((unsigned)k8 * 16 + (wn * 4 + n)) * 32 + lane) * 2]);
                bu[n] = *reinterpret_cast<uint2*>(
                    &sBu[boff + (((unsigned)k8 * 16 + (wn * 4 + n)) * 32 + lane) * 2]);
            }
#pragma unroll
            for (int m = 0; m < 4; m++)
#pragma unroll
                for (int n = 0; n < 4; n++) {
                    mma_tf32(dg[m][n], a[m], bg[n]);
                    mma_tf32(du[m][n], a[m], bu[n]);
                }
        }

        if (iter + 1 < NIT) {
            __syncthreads();
            unsigned na = (unsigned)(buf ^ 1) * G1_SA;
            unsigned nb = (unsigned)(buf ^ 1) * G1_SB;
#pragma unroll
            for (int it = 0; it < 2; it++) {
                sA[na + abase[it] + 0]  = f2tf(pA[it].x);
                sA[na + abase[it] + 4]  = f2tf(pA[it].y);
                sA[na + abase[it] + 8]  = f2tf(pA[it].z);
                sA[na + abase[it] + 12] = f2tf(pA[it].w);
                sBg[nb + bbase[it] + 0]  = f2tf(pG[it].x);
                sBg[nb + bbase[it] + 8]  = f2tf(pG[it].y);
                sBg[nb + bbase[it] + 16] = f2tf(pG[it].z);
                sBg[nb + bbase[it] + 24] = f2tf(pG[it].w);
                sBu[nb + bbase[it] + 0]  = f2tf(pU[it].x);
                sBu[nb + bbase[it] + 8]  = f2tf(pU[it].y);
                sBu[nb + bbase[it] + 16] = f2tf(pU[it].z);
                sBu[nb + bbase[it] + 24] = f2tf(pU[it].w);
            }
            __syncthreads();
        }
    }

    // epilogue: silu(g)*u
    size_t base = (size_t)e * MAXP;
    int cg = lane >> 2, ct = lane & 3;
#pragma unroll
    for (int m = 0; m < 4; m++) {
        int rb = row0 + wm * 64 + m * 16 + cg;
#pragma unroll
        for (int n = 0; n < 4; n++) {
            int cb = col0 + wn * 32 + n * 8 + 2 * ct;
            if (rb < cnt) {
                float gv0 = dg[m][n][0], gv1 = dg[m][n][1];
                float s0 = gv0 / (1.f + expf(-gv0));
                float s1 = gv1 / (1.f + expf(-gv1));
                float2 o = make_float2(s0 * du[m][n][0], s1 * du[m][n][1]);
                *reinterpret_cast<float2*>(&g_act[(base + rb) * NI + cb]) = o;
            }
            if (rb + 8 < cnt) {
                float gv2 = dg[m][n][2], gv3 = dg[m][n][3];
                float s2 = gv2 / (1.f + expf(-gv2));
                float s3 = gv3 / (1.f + expf(-gv3));
                float2 o = make_float2(s2 * du[m][n][2], s3 * du[m][n][3]);
                *reinterpret_cast<float2*>(&g_act[(base + rb + 8) * NI + cb]) = o;
            }
        }
    }
}

// ---------------------------------------------------------------------------
// GEMM2 (tf32 TC): pout = wt * (act . w_down).  Block 128x256, BK=16.
// 8 warps as 2(m) x 4(n); warp tile 64x64.
#define G2_SA (2 * 8 * 32 * 4)     // 2048 unsigned per buffer (128x16)
#define G2_SB (2 * 32 * 32 * 2)    // 4096 unsigned per buffer (16x256)

__global__ __launch_bounds__(256) void gemm2_tc(const float* __restrict__ wd) {
    int e    = blockIdx.z;
    int cnt  = g_cnt[e];
    int row0 = blockIdx.y * 128;
    if (row0 >= cnt) return;
    int col0 = blockIdx.x * 256;

    __shared__ unsigned sA[2 * G2_SA];   // 16KB
    __shared__ unsigned sB[2 * G2_SB];   // 32KB

    int tid  = threadIdx.x;
    int lane = tid & 31;
    int wid  = tid >> 5;
    int wm   = wid >> 2;      // 0..1
    int wn   = wid & 3;       // 0..3 -> cols wn*64

    size_t pbase = (size_t)e * MAXP;

    // --- A loader: 2 float4/thread ---
    int ac[2];
    bool aval[2];
    unsigned abase[2];
    const float* aptr[2];
#pragma unroll
    for (int it = 0; it < 2; it++) {
        int f = tid + 256 * it;
        int r = f >> 2;
        int c = (f & 3) * 4;
        ac[it] = c;
        aval[it] = (row0 + r) < cnt;
        aptr[it] = &g_act[(pbase + row0 + r) * NI + c];
        int k8  = c >> 3;
        int reg = ((r >> 3) & 1) + 2 * ((c >> 2) & 1);
        abase[it] = (((unsigned)k8 * 8 + (r >> 4)) * 32 + (r & 7) * 4) * 4 + reg;
    }
    // --- B loader: 4 float4/thread; krow = f>>6, ncol = (f&63)*4 ---
    const float* wdP[4];
    unsigned bbase[4];
#pragma unroll
    for (int it = 0; it < 4; it++) {
        int f    = tid + 256 * it;
        int krow = f >> 6;            // 0..15
        int ncol = (f & 63) * 4;      // 0..252
        wdP[it] = wd + (size_t)e * NI * NH + (size_t)krow * NH + col0 + ncol;
        int k8  = krow >> 3;
        int kk  = krow & 7;
        bbase[it] = (((unsigned)k8 * 32 + (ncol >> 3)) * 32 + (ncol & 7) * 4 + (kk & 3)) * 2
                    + (kk >> 2);
    }

    float d[4][8][4] = {};

    float4 pA[2], pB[4];
#pragma unroll
    for (int it = 0; it < 2; it++) {
        pA[it] = make_float4(0.f, 0.f, 0.f, 0.f);
        if (aval[it]) pA[it] = *reinterpret_cast<const float4*>(aptr[it]);
    }
#pragma unroll
    for (int it = 0; it < 4; it++)
        pB[it] = *reinterpret_cast<const float4*>(wdP[it]);
#pragma unroll
    for (int it = 0; it < 2; it++) {
        sA[abase[it] + 0]  = f2tf(pA[it].x);
        sA[abase[it] + 4]  = f2tf(pA[it].y);
        sA[abase[it] + 8]  = f2tf(pA[it].z);
        sA[abase[it] + 12] = f2tf(pA[it].w);
    }
#pragma unroll
    for (int it = 0; it < 4; it++) {
        sB[bbase[it] + 0]  = f2tf(pB[it].x);  sB[bbase[it] + 8]  = f2tf(pB[it].y);
        sB[bbase[it] + 16] = f2tf(pB[it].z);  sB[bbase[it] + 24] = f2tf(pB[it].w);
    }
    __syncthreads();

    const int NIT = NI / BK;  // 32
    for (int iter = 0; iter < NIT; iter++) {
        int buf = iter & 1;
        if (iter + 1 < NIT) {
            int k0 = (iter + 1) * BK;
#pragma unroll
            for (int it = 0; it < 2; it++) {
                pA[it] = make_float4(0.f, 0.f, 0.f, 0.f);
                if (aval[it])
                    pA[it] = *reinterpret_cast<const float4*>(aptr[it] + k0);
            }
#pragma unroll
            for (int it = 0; it < 4; it++)
                pB[it] = *reinterpret_cast<const float4*>(wdP[it] + (size_t)k0 * NH);
        }

        unsigned aoff = (unsigned)buf * G2_SA;
        unsigned boff = (unsigned)buf * G2_SB;
#pragma unroll
        for (int k8 = 0; k8 < 2; k8++) {
            uint4 a[4];
#pragma unroll
            for (int m = 0; m < 4; m++)
                a[m] = *reinterpret_cast<uint4*>(
                    &sA[aoff + (((unsigned)k8 * 8 + (wm * 4 + m)) * 32 + lane) * 4]);
            uint2 b[8];
#pragma unroll
            for (int n = 0; n < 8; n++)
                b[n] = *reinterpret_cast<uint2*>(
                    &sB[boff + (((unsigned)k8 * 32 + (wn * 8 + n)) * 32 + lane) * 2]);
#pragma unroll
            for (int m = 0; m < 4; m++)
#pragma unroll
                for (int n = 0; n < 8; n++)
                    mma_tf32(d[m][n], a[m], b[n]);
        }

        if (iter + 1 < NIT) {
            __syncthreads();
            unsigned na = (unsigned)(buf ^ 1) * G2_SA;
            unsigned nb = (unsigned)(buf ^ 1) * G2_SB;
#pragma unroll
            for (int it = 0; it < 2; it++) {
                sA[na + abase[it] + 0]  = f2tf(pA[it].x);
                sA[na + abase[it] + 4]  = f2tf(pA[it].y);
                sA[na + abase[it] + 8]  = f2tf(pA[it].z);
                sA[na + abase[it] + 12] = f2tf(pA[it].w);
            }
#pragma unroll
            for (int it = 0; it < 4; it++) {
                sB[nb + bbase[it] + 0]  = f2tf(pB[it].x);
                sB[nb + bbase[it] + 8]  = f2tf(pB[it].y);
                sB[nb + bbase[it] + 16] = f2tf(pB[it].z);
                sB[nb + bbase[it] + 24] = f2tf(pB[it].w);
            }
            __syncthreads();
        }
    }

    int cg = lane >> 2, ct = lane & 3;
#pragma unroll
    for (int m = 0; m < 4; m++) {
        int rb = row0 + wm * 64 + m * 16 + cg;
        float w0 = (rb     < cnt) ? g_wt[e * MAXP + rb]     : 0.f;
        float w1 = (rb + 8 < cnt) ? g_wt[e * MAXP + rb + 8] : 0.f;
#pragma unroll
        for (int n = 0; n < 8; n++) {
            int cb = col0 + wn * 64 + n * 8 + 2 * ct;
            if (rb < cnt) {
                float2 o = make_float2(d[m][n][0] * w0, d[m][n][1] * w0);
                *reinterpret_cast<float2*>(&g_pout[(pbase + rb) * NH + cb]) = o;
            }
            if (rb + 8 < cnt) {
                float2 o = make_float2(d[m][n][2] * w1, d[m][n][3] * w1);
                *reinterpret_cast<float2*>(&g_pout[(pbase + rb + 8) * NH + cb]) = o;
            }
        }
    }
}

// ---------------------------------------------------------------------------
// Combine: out[t] += sum of this token's pair outputs (deterministic order).
__global__ void combine_kernel(float* __restrict__ out) {
    int t  = blockIdx.x;
    int np = g_tk_n[t];
    int p[TOPK];
    for (int j = 0; j < np; j++) p[j] = g_tk_pair[t * TOPK + j];
    for (int h = threadIdx.x; h < NH; h += 256) {
        float s = 0.f;
        for (int j = 0; j < np; j++)
            s += g_pout[(size_t)p[j] * NH + h];
        out[(size_t)t * NH + h] += s;
    }
}

// ---------------------------------------------------------------------------
extern "C" void kernel_launch(void* const* d_in, const int* in_sizes, int n_in,
                              void* d_out, int out_size) {
    (void)in_sizes; (void)n_in; (void)out_size;
    const float* x    = (const float*)d_in[0];
    const float* rw   = (const float*)d_in[1];
    const float* bias = (const float*)d_in[2];
    const float* wg   = (const float*)d_in[3];
    const float* wu   = (const float*)d_in[4];
    const float* wd   = (const float*)d_in[5];
    float* out = (float*)d_out;

    reset_kernel<<<1, 32>>>();
    router_kernel<<<T_TOK, 256>>>(x, rw, bias, out);

    dim3 g1(NI / 128, MAXP / 128, NE);
    gemm1_tc<<<g1, 256>>>(x, wg, wu);

    dim3 g2(NH / 256, MAXP / 128, NE);
    gemm2_tc<<<g2, 256>>>(wd);

    combine_kernel<<<T_TOK, 256>>>(out);
}

// round 7
// speedup vs baseline: 1.0919x; 1.0919x over previous
#include <cuda_runtime.h>
#include <math.h>

#define T_TOK 4096
#define NH 1024          // hidden
#define NI 512           // intermediate
#define NE 16            // real experts
#define NSLOT 32         // real + zero slots
#define TOPK 4
#define MAXP 4096        // max pairs per expert (<= T)

// GEMM tiling (R5 config: block 128x64, 8 warps as 4m x 2n, warp tile 32x32)
#define BM 128
#define BN 64
#define BK 16

// ---- static device scratch (no runtime allocation allowed) ----
__device__ int   g_cnt[NE];                       // pairs per expert
__device__ int   g_tok[NE * MAXP];                // token index per pair slot
__device__ float g_wt [NE * MAXP];                // routing weight per pair slot
__device__ int   g_tk_n[T_TOK];                   // real experts chosen per token
__device__ int   g_tk_pair[T_TOK * TOPK];         // pair indices per token (topk order)
__device__ float g_act [(size_t)NE * MAXP * NI];  // SwiGLU activations
__device__ float g_pout[(size_t)NE * MAXP * NH];  // per-pair down output

// ---------------------------------------------------------------------------
__device__ __forceinline__ unsigned f2tf(float f) {
    unsigned r;
    asm("cvt.rna.tf32.f32 %0, %1;" : "=r"(r) : "f"(f));
    return r;
}

__device__ __forceinline__ void mma_tf32(float* d, const uint4& a, const uint2& b) {
    asm volatile(
        "mma.sync.aligned.m16n8k8.row.col.f32.tf32.tf32.f32 "
        "{%0,%1,%2,%3}, {%4,%5,%6,%7}, {%8,%9}, {%0,%1,%2,%3};"
        : "+f"(d[0]), "+f"(d[1]), "+f"(d[2]), "+f"(d[3])
        : "r"(a.x), "r"(a.y), "r"(a.z), "r"(a.w), "r"(b.x), "r"(b.y));
}

// ---------------------------------------------------------------------------
__global__ void reset_kernel() {
    int i = threadIdx.x;
    if (i < NE) g_cnt[i] = 0;
}

// ---------------------------------------------------------------------------
// Router: one block (256 threads) per token.
__global__ void router_kernel(const float* __restrict__ x,
                              const float* __restrict__ rw,
                              const float* __restrict__ bias,
                              float* __restrict__ out) {
    int t = blockIdx.x;
    __shared__ float sc[NSLOT];
    __shared__ float s_zero;
    int tid  = threadIdx.x;           // 256
    int slot = tid >> 3;              // 32 slots, 8 threads each
    int sub  = tid & 7;
    const float* xr = x  + (size_t)t * NH;
    const float* wr = rw + (size_t)slot * NH;

    float acc = 0.f;
    for (int h = sub * 4; h < NH; h += 32) {
        float4 xv = *reinterpret_cast<const float4*>(xr + h);
        float4 wv = *reinterpret_cast<const float4*>(wr + h);
        acc += xv.x * wv.x + xv.y * wv.y + xv.z * wv.z + xv.w * wv.w;
    }
    acc += __shfl_down_sync(0xffffffffu, acc, 4, 8);
    acc += __shfl_down_sync(0xffffffffu, acc, 2, 8);
    acc += __shfl_down_sync(0xffffffffu, acc, 1, 8);
    if (sub == 0) sc[slot] = acc;
    __syncthreads();

    if (tid == 0) {
        float mx = -1e30f;
        for (int i = 0; i < NSLOT; i++) mx = fmaxf(mx, sc[i]);
        float e[NSLOT], sum = 0.f;
        for (int i = 0; i < NSLOT; i++) { e[i] = expf(sc[i] - mx); sum += e[i]; }
        float inv = 1.f / sum;
        float sb[NSLOT];
        for (int i = 0; i < NSLOT; i++) {
            sc[i] = e[i] * inv;            // raw score (weight source)
            sb[i] = sc[i] + bias[i];       // selection score
        }
        float zero_w = 0.f;
        int tkn = 0;
        for (int kk = 0; kk < TOPK; kk++) {
            int bi = 0; float bv = -1e30f;
            for (int i = 0; i < NSLOT; i++)
                if (sb[i] > bv) { bv = sb[i]; bi = i; }
            sb[bi] = -1e30f;
            float w = sc[bi];
            if (bi < NE) {
                int s2 = atomicAdd(&g_cnt[bi], 1);
                g_tok[bi * MAXP + s2] = t;
                g_wt [bi * MAXP + s2] = w;
                g_tk_pair[t * TOPK + tkn] = bi * MAXP + s2;
                tkn++;
            } else {
                zero_w += w;
            }
        }
        g_tk_n[t] = tkn;
        s_zero = zero_w;
    }
    __syncthreads();

    float zw = s_zero;
    for (int h = tid; h < NH; h += 256)
        out[(size_t)t * NH + h] = zw * xr[h];
}

// ---------------------------------------------------------------------------
// GEMM1 (tf32 TC, depth-2 A prefetch / depth-1 B, double-buffered smem):
// act = silu(X.Wg)*(X.Wu).  Block 128x64, 8 warps (4m x 2n), warp tile 32x32.
#define SA_BUF (8 * 32 * 4 * 2)   // per-buffer unsigned count for A  (k8=2)
#define SB_BUF (8 * 32 * 2 * 2)   // per-buffer unsigned count for B  (k8=2)

__global__ __launch_bounds__(256) void gemm1_tc(const float* __restrict__ x,
                                                const float* __restrict__ wg,
                                                const float* __restrict__ wu) {
    int e    = blockIdx.z;
    int cnt  = g_cnt[e];
    int row0 = blockIdx.y * BM;
    if (row0 >= cnt) return;
    int col0 = blockIdx.x * BN;

    __shared__ unsigned sA [2 * SA_BUF];   // 16KB
    __shared__ unsigned sBg[2 * SB_BUF];   // 8KB
    __shared__ unsigned sBu[2 * SB_BUF];   // 8KB

    int tid  = threadIdx.x;
    int lane = tid & 31;
    int wid  = tid >> 5;
    int wm   = wid >> 1;      // 0..3
    int wn   = wid & 1;       // 0..1

    // --- A loader precompute: 2 float4 per thread ---
    int tok[2];
    unsigned abase[2];
    int ac[2];
#pragma unroll
    for (int it = 0; it < 2; it++) {
        int f = tid + 256 * it;
        int r = f >> 2;
        int c = (f & 3) * 4;
        ac[it] = c;
        int rr = row0 + r;
        tok[it] = (rr < cnt) ? g_tok[e * MAXP + rr] : -1;
        int k8  = c >> 3;
        int reg = ((r >> 3) & 1) + 2 * ((c >> 2) & 1);
        abase[it] = (((unsigned)k8 * 8 + (r >> 4)) * 32 + (r & 7) * 4) * 4 + reg;
    }
    // --- B loader precompute ---
    int bkr = tid >> 4;             // 0..15 (k row within tile)
    int bc  = (tid & 15) * 4;       // 0..60 (col)
    const float* wgB = wg + (size_t)e * NH * NI + (size_t)bkr * NI + col0 + bc;
    const float* wuB = wu + (size_t)e * NH * NI + (size_t)bkr * NI + col0 + bc;
    int bk8  = bkr >> 3;
    int bkk  = bkr & 7;
    int breg = bkk >> 2;
    int bt   = bkk & 3;
    int bnt  = bc >> 3;
    unsigned bbase = (((unsigned)bk8 * 8 + bnt) * 32 + (bc & 7) * 4 + bt) * 2 + breg;

    float dg[2][4][4] = {};
    float du[2][4][4] = {};

    // prefetch registers: A has two sets (depth-2); B one set (depth-1)
    float4 pAs[2][2];
    float4 pG, pU;

    // --- prologue: stage tile 0 directly ---
    {
        float4 a0[2];
#pragma unroll
        for (int it = 0; it < 2; it++) {
            a0[it] = make_float4(0.f, 0.f, 0.f, 0.f);
            if (tok[it] >= 0)
                a0[it] = *reinterpret_cast<const float4*>(x + (size_t)tok[it] * NH + ac[it]);
        }
        float4 g0 = *reinterpret_cast<const float4*>(wgB);
        float4 u0 = *reinterpret_cast<const float4*>(wuB);
#pragma unroll
        for (int it = 0; it < 2; it++) {
            sA[abase[it] + 0]  = f2tf(a0[it].x);
            sA[abase[it] + 4]  = f2tf(a0[it].y);
            sA[abase[it] + 8]  = f2tf(a0[it].z);
            sA[abase[it] + 12] = f2tf(a0[it].w);
        }
        sBg[bbase + 0]  = f2tf(g0.x);  sBg[bbase + 8]  = f2tf(g0.y);
        sBg[bbase + 16] = f2tf(g0.z);  sBg[bbase + 24] = f2tf(g0.w);
        sBu[bbase + 0]  = f2tf(u0.x);  sBu[bbase + 8]  = f2tf(u0.y);
        sBu[bbase + 16] = f2tf(u0.z);  sBu[bbase + 24] = f2tf(u0.w);
    }
    // prefetch A tile 1 into set 1
#pragma unroll
    for (int it = 0; it < 2; it++) {
        pAs[1][it] = make_float4(0.f, 0.f, 0.f, 0.f);
        if (tok[it] >= 0)
            pAs[1][it] = *reinterpret_cast<const float4*>(x + (size_t)tok[it] * NH + BK + ac[it]);
    }
    __syncthreads();

    const int NIT = NH / BK;  // 64
#pragma unroll 2
    for (int k = 0; k < NIT; k++) {
        int buf = k & 1;
        // depth-2 A prefetch: issue LDG for tile k+2 into set (k&1)
        if (k + 2 < NIT) {
            int k0 = (k + 2) * BK;
#pragma unroll
            for (int it = 0; it < 2; it++) {
                pAs[buf][it] = make_float4(0.f, 0.f, 0.f, 0.f);
                if (tok[it] >= 0)
                    pAs[buf][it] = *reinterpret_cast<const float4*>(
                                       x + (size_t)tok[it] * NH + k0 + ac[it]);
            }
        }
        // depth-1 B prefetch: tile k+1
        if (k + 1 < NIT) {
            int k0 = (k + 1) * BK;
            pG = *reinterpret_cast<const float4*>(wgB + (size_t)k0 * NI);
            pU = *reinterpret_cast<const float4*>(wuB + (size_t)k0 * NI);
        }

        unsigned aoff = (unsigned)buf * SA_BUF;
        unsigned boff = (unsigned)buf * SB_BUF;
#pragma unroll
        for (int k8 = 0; k8 < 2; k8++) {
            uint4 a[2];
#pragma unroll
            for (int m = 0; m < 2; m++)
                a[m] = *reinterpret_cast<uint4*>(
                    &sA[aoff + (((unsigned)k8 * 8 + (wm * 2 + m)) * 32 + lane) * 4]);
            uint2 bg[4], bu[4];
#pragma unroll
            for (int n = 0; n < 4; n++) {
                bg[n] = *reinterpret_cast<uint2*>(
                    &sBg[boff + (((unsigned)k8 * 8 + (wn * 4 + n)) * 32 + lane) * 2]);
                bu[n] = *reinterpret_cast<uint2*>(
                    &sBu[boff + (((unsigned)k8 * 8 + (wn * 4 + n)) * 32 + lane) * 2]);
            }
#pragma unroll
            for (int m = 0; m < 2; m++)
#pragma unroll
                for (int n = 0; n < 4; n++) {
                    mma_tf32(dg[m][n], a[m], bg[n]);
                    mma_tf32(du[m][n], a[m], bu[n]);
                }
        }

        if (k + 1 < NIT) {
            int nset = (k + 1) & 1;   // A regs for tile k+1
            __syncthreads();
            unsigned na = (unsigned)(buf ^ 1) * SA_BUF;
            unsigned nb = (unsigned)(buf ^ 1) * SB_BUF;
#pragma unroll
            for (int it = 0; it < 2; it++) {
                sA[na + abase[it] + 0]  = f2tf(pAs[nset][it].x);
                sA[na + abase[it] + 4]  = f2tf(pAs[nset][it].y);
                sA[na + abase[it] + 8]  = f2tf(pAs[nset][it].z);
                sA[na + abase[it] + 12] = f2tf(pAs[nset][it].w);
            }
            sBg[nb + bbase + 0]  = f2tf(pG.x);  sBg[nb + bbase + 8]  = f2tf(pG.y);
            sBg[nb + bbase + 16] = f2tf(pG.z);  sBg[nb + bbase + 24] = f2tf(pG.w);
            sBu[nb + bbase + 0]  = f2tf(pU.x);  sBu[nb + bbase + 8]  = f2tf(pU.y);
            sBu[nb + bbase + 16] = f2tf(pU.z);  sBu[nb + bbase + 24] = f2tf(pU.w);
            __syncthreads();
        }
    }

    // epilogue: silu(g)*u
    size_t base = (size_t)e * MAXP;
    int cg = lane >> 2, ct = lane & 3;
#pragma unroll
    for (int m = 0; m < 2; m++) {
        int rb = row0 + wm * 32 + m * 16 + cg;
#pragma unroll
        for (int n = 0; n < 4; n++) {
            int cb = col0 + wn * 32 + n * 8 + 2 * ct;
            if (rb < cnt) {
                float gv0 = dg[m][n][0], gv1 = dg[m][n][1];
                float s0 = gv0 / (1.f + expf(-gv0));
                float s1 = gv1 / (1.f + expf(-gv1));
                float2 o = make_float2(s0 * du[m][n][0], s1 * du[m][n][1]);
                *reinterpret_cast<float2*>(&g_act[(base + rb) * NI + cb]) = o;
            }
            if (rb + 8 < cnt) {
                float gv2 = dg[m][n][2], gv3 = dg[m][n][3];
                float s2 = gv2 / (1.f + expf(-gv2));
                float s3 = gv3 / (1.f + expf(-gv3));
                float2 o = make_float2(s2 * du[m][n][2], s3 * du[m][n][3]);
                *reinterpret_cast<float2*>(&g_act[(base + rb + 8) * NI + cb]) = o;
            }
        }
    }
}

// ---------------------------------------------------------------------------
// GEMM2 (tf32 TC, depth-2 A prefetch / depth-1 B): pout = wt * (act . w_down)
__global__ __launch_bounds__(256) void gemm2_tc(const float* __restrict__ wd) {
    int e    = blockIdx.z;
    int cnt  = g_cnt[e];
    int row0 = blockIdx.y * BM;
    if (row0 >= cnt) return;
    int col0 = blockIdx.x * BN;

    __shared__ unsigned sA[2 * SA_BUF];   // 16KB
    __shared__ unsigned sB[2 * SB_BUF];   // 8KB

    int tid  = threadIdx.x;
    int lane = tid & 31;
    int wid  = tid >> 5;
    int wm   = wid >> 1;
    int wn   = wid & 1;

    size_t pbase = (size_t)e * MAXP;

    int ac[2];
    bool aval[2];
    unsigned abase[2];
    const float* aptr[2];
#pragma unroll
    for (int it = 0; it < 2; it++) {
        int f = tid + 256 * it;
        int r = f >> 2;
        int c = (f & 3) * 4;
        ac[it] = c;
        aval[it] = (row0 + r) < cnt;
        aptr[it] = &g_act[(pbase + row0 + r) * NI + c];
        int k8  = c >> 3;
        int reg = ((r >> 3) & 1) + 2 * ((c >> 2) & 1);
        abase[it] = (((unsigned)k8 * 8 + (r >> 4)) * 32 + (r & 7) * 4) * 4 + reg;
    }
    int bkr = tid >> 4;
    int bc  = (tid & 15) * 4;
    const float* wdB = wd + (size_t)e * NI * NH + (size_t)bkr * NH + col0 + bc;
    int bk8  = bkr >> 3;
    int bkk  = bkr & 7;
    int breg = bkk >> 2;
    int bt   = bkk & 3;
    int bnt  = bc >> 3;
    unsigned bbase = (((unsigned)bk8 * 8 + bnt) * 32 + (bc & 7) * 4 + bt) * 2 + breg;

    float d[2][4][4] = {};

    float4 pAs[2][2];
    float4 pB;

    // prologue: stage tile 0 directly
    {
        float4 a0[2];
#pragma unroll
        for (int it = 0; it < 2; it++) {
            a0[it] = make_float4(0.f, 0.f, 0.f, 0.f);
            if (aval[it]) a0[it] = *reinterpret_cast<const float4*>(aptr[it]);
        }
        float4 b0 = *reinterpret_cast<const float4*>(wdB);
#pragma unroll
        for (int it = 0; it < 2; it++) {
            sA[abase[it] + 0]  = f2tf(a0[it].x);
            sA[abase[it] + 4]  = f2tf(a0[it].y);
            sA[abase[it] + 8]  = f2tf(a0[it].z);
            sA[abase[it] + 12] = f2tf(a0[it].w);
        }
        sB[bbase + 0]  = f2tf(b0.x);  sB[bbase + 8]  = f2tf(b0.y);
        sB[bbase + 16] = f2tf(b0.z);  sB[bbase + 24] = f2tf(b0.w);
    }
    // prefetch A tile 1 into set 1
#pragma unroll
    for (int it = 0; it < 2; it++) {
        pAs[1][it] = make_float4(0.f, 0.f, 0.f, 0.f);
        if (aval[it]) pAs[1][it] = *reinterpret_cast<const float4*>(aptr[it] + BK);
    }
    __syncthreads();

    const int NIT = NI / BK;  // 32
#pragma unroll 2
    for (int k = 0; k < NIT; k++) {
        int buf = k & 1;
        if (k + 2 < NIT) {
            int k0 = (k + 2) * BK;
#pragma unroll
            for (int it = 0; it < 2; it++) {
                pAs[buf][it] = make_float4(0.f, 0.f, 0.f, 0.f);
                if (aval[it])
                    pAs[buf][it] = *reinterpret_cast<const float4*>(aptr[it] + k0);
            }
        }
        if (k + 1 < NIT) {
            int k0 = (k + 1) * BK;
            pB = *reinterpret_cast<const float4*>(wdB + (size_t)k0 * NH);
        }

        unsigned aoff = (unsigned)buf * SA_BUF;
        unsigned boff = (unsigned)buf * SB_BUF;
#pragma unroll
        for (int k8 = 0; k8 < 2; k8++) {
            uint4 a[2];
#pragma unroll
            for (int m = 0; m < 2; m++)
                a[m] = *reinterpret_cast<uint4*>(
                    &sA[aoff + (((unsigned)k8 * 8 + (wm * 2 + m)) * 32 + lane) * 4]);
            uint2 b[4];
#pragma unroll
            for (int n = 0; n < 4; n++)
                b[n] = *reinterpret_cast<uint2*>(
                    &sB[boff + (((unsigned)k8 * 8 + (wn * 4 + n)) * 32 + lane) * 2]);
#pragma unroll
            for (int m = 0; m < 2; m++)
#pragma unroll
                for (int n = 0; n < 4; n++)
                    mma_tf32(d[m][n], a[m], b[n]);
        }

        if (k + 1 < NIT) {
            int nset = (k + 1) & 1;
            __syncthreads();
            unsigned na = (unsigned)(buf ^ 1) * SA_BUF;
            unsigned nb = (unsigned)(buf ^ 1) * SB_BUF;
#pragma unroll
            for (int it = 0; it < 2; it++) {
                sA[na + abase[it] + 0]  = f2tf(pAs[nset][it].x);
                sA[na + abase[it] + 4]  = f2tf(pAs[nset][it].y);
                sA[na + abase[it] + 8]  = f2tf(pAs[nset][it].z);
                sA[na + abase[it] + 12] = f2tf(pAs[nset][it].w);
            }
            sB[nb + bbase + 0]  = f2tf(pB.x);  sB[nb + bbase + 8]  = f2tf(pB.y);
            sB[nb + bbase + 16] = f2tf(pB.z);  sB[nb + bbase + 24] = f2tf(pB.w);
            __syncthreads();
        }
    }

    int cg = lane >> 2, ct = lane & 3;
#pragma unroll
    for (int m = 0; m < 2; m++) {
        int rb = row0 + wm * 32 + m * 16 + cg;
        float w0 = (rb     < cnt) ? g_wt[e * MAXP + rb]     : 0.f;
        float w1 = (rb + 8 < cnt) ? g_wt[e * MAXP + rb + 8] : 0.f;
#pragma unroll
        for (int n = 0; n < 4; n++) {
            int cb = col0 + wn * 32 + n * 8 + 2 * ct;
            if (rb < cnt) {
                float2 o = make_float2(d[m][n][0] * w0, d[m][n][1] * w0);
                *reinterpret_cast<float2*>(&g_pout[(pbase + rb) * NH + cb]) = o;
            }
            if (rb + 8 < cnt) {
                float2 o = make_float2(d[m][n][2] * w1, d[m][n][3] * w1);
                *reinterpret_cast<float2*>(&g_pout[(pbase + rb + 8) * NH + cb]) = o;
            }
        }
    }
}

// ---------------------------------------------------------------------------
// Combine (vectorized): out[t] += sum over this token's pairs (topk order).
// 256 threads/block, one float4 per thread (NH/4 == 256).
__global__ void combine_kernel(float* __restrict__ out) {
    int t  = blockIdx.x;
    int np = g_tk_n[t];
    int p[TOPK];
    for (int j = 0; j < np; j++) p[j] = g_tk_pair[t * TOPK + j];
    int h4 = threadIdx.x;      // 0..255 -> float4 index
    float4 s = *reinterpret_cast<float4*>(&out[(size_t)t * NH + h4 * 4]);
    for (int j = 0; j < np; j++) {
        float4 v = *reinterpret_cast<const float4*>(&g_pout[(size_t)p[j] * NH + h4 * 4]);
        s.x += v.x; s.y += v.y; s.z += v.z; s.w += v.w;
    }
    *reinterpret_cast<float4*>(&out[(size_t)t * NH + h4 * 4]) = s;
}

// ---------------------------------------------------------------------------
extern "C" void kernel_launch(void* const* d_in, const int* in_sizes, int n_in,
                              void* d_out, int out_size) {
    (void)in_sizes; (void)n_in; (void)out_size;
    const float* x    = (const float*)d_in[0];
    const float* rw   = (const float*)d_in[1];
    const float* bias = (const float*)d_in[2];
    const float* wg   = (const float*)d_in[3];
    const float* wu   = (const float*)d_in[4];
    const float* wd   = (const float*)d_in[5];
    float* out = (float*)d_out;

    reset_kernel<<<1, 32>>>();
    router_kernel<<<T_TOK, 256>>>(x, rw, bias, out);

    dim3 g1(NI / BN, MAXP / BM, NE);
    gemm1_tc<<<g1, 256>>>(x, wg, wu);

    dim3 g2(NH / BN, MAXP / BM, NE);
    gemm2_tc<<<g2, 256>>>(wd);

    combine_kernel<<<T_TOK, 256>>>(out);
}